// round 8
// baseline (speedup 1.0000x reference)
#include <cuda_runtime.h>
#include <cuda_bf16.h>
#include <math_constants.h>

#define ROWS 8192
#define COLS 8192
#define NG   64
#define TPB  32                       // one warp per block; thread = row
#define CCHUNK 1024                   // columns per block
#define NB    (CCHUNK / 32)           // 32 superbatches of 32 columns
#define NWIN  (COLS / 4)              // 2048 4-column windows
#define WPC   (CCHUNK / 4)            // 256 windows per chunk
#define NCHUNK (COLS / CCHUNK)        // 8
#define NROWBLK (ROWS / TPB)          // 256
#define NOUT (ROWS * NG)              // 524288 per output tensor

// Partial min/max per (chunk, row, group): plain stores, no atomics. 33.5 MB.
__device__ float2   g_part[(size_t)NCHUNK * ROWS * NG];
// Arrival counters per row-block (zero-initialized at load; last block resets).
__device__ unsigned g_cnt[NROWBLK];
// Per-window packed group ids: raw, and dup-remapped (dups -> group 64).
__device__ unsigned g_rawp[NWIN];
__device__ unsigned g_remp[NWIN];

// ---- Prep: detect duplicate groups within each aligned 4-column window ----
__global__ void obs_prep_kernel(const int* __restrict__ gidx) {
    int w = blockIdx.x * blockDim.x + threadIdx.x;
    if (w >= NWIN) return;
    int4 g = ((const int4*)gidx)[w];
    unsigned b0 = (unsigned)g.x, b1 = (unsigned)g.y;
    unsigned b2 = (unsigned)g.z, b3 = (unsigned)g.w;
    unsigned r1 = (b1 == b0) ? 64u : b1;
    unsigned r2 = (b2 == b0 || b2 == b1) ? 64u : b2;
    unsigned r3 = (b3 == b0 || b3 == b1 || b3 == b2) ? 64u : b3;
    g_rawp[w] = b0 | (b1 << 8) | (b2 << 16) | (b3 << 24);
    g_remp[w] = b0 | (r1 << 8) | (r2 << 16) | (r3 << 24);
}

__global__ __launch_bounds__(TPB, 12) void obs_fused_kernel(
    const float* __restrict__ obs, const int* __restrict__ gidx,
    float* __restrict__ out)
{
    // 65 groups: group 64 = dummy sink for intra-window duplicates.
    __shared__ float2 sacc[65 * TPB];              // 16.64 KB
    __shared__ __align__(8) uint2 swin[WPC];       // 2 KB {remapped, raw}

    const int t   = threadIdx.x;
    const int bx  = blockIdx.x;         // chunk id
    const int by  = blockIdx.y;         // row-block id
    const int c0  = bx * CCHUNK;
    const int row = by * TPB + t;

    // Stage window descriptors (L2-hot after first blocks).
    #pragma unroll
    for (int i = t; i < WPC; i += TPB)
        swin[i] = make_uint2(g_remp[bx * WPC + i], g_rawp[bx * WPC + i]);

    #pragma unroll
    for (int g = 0; g < 65; g++)
        sacc[g * TPB + t] = make_float2(CUDART_INF_F, -CUDART_INF_F);
    __syncthreads();   // TPB==32: warp barrier, cheap

    const float4* rp = (const float4*)(obs + (size_t)row * COLS + c0);
    char* accbase = (char*)sacc + t * 8;   // lane-private column of sacc

    // One 4-column window: remapped ids are pairwise-distinct => batch the
    // 4 RMWs read-all/compute-all/write-all (full ILP, no false chains).
    // Rare duplicates (raw != remapped bytes) fixed up serially after.
    #define WIN(F4, WI) do {                                              \
        uint2 _rr = swin[(WI)];                                           \
        unsigned _o0 = __byte_perm(_rr.x, 0, 0x4404);                     \
        unsigned _o1 = __byte_perm(_rr.x, 0, 0x4414);                     \
        unsigned _o2 = __byte_perm(_rr.x, 0, 0x4424);                     \
        unsigned _o3 = __byte_perm(_rr.x, 0, 0x4434);                     \
        float2* _p0 = (float2*)(accbase + _o0);                           \
        float2* _p1 = (float2*)(accbase + _o1);                           \
        float2* _p2 = (float2*)(accbase + _o2);                           \
        float2* _p3 = (float2*)(accbase + _o3);                           \
        float2 _m0 = *_p0, _m1 = *_p1, _m2 = *_p2, _m3 = *_p3;            \
        _m0.x = fminf(_m0.x, (F4).x); _m0.y = fmaxf(_m0.y, (F4).x);       \
        _m1.x = fminf(_m1.x, (F4).y); _m1.y = fmaxf(_m1.y, (F4).y);       \
        _m2.x = fminf(_m2.x, (F4).z); _m2.y = fmaxf(_m2.y, (F4).z);       \
        _m3.x = fminf(_m3.x, (F4).w); _m3.y = fmaxf(_m3.y, (F4).w);       \
        *_p0 = _m0; *_p1 = _m1; *_p2 = _m2; *_p3 = _m3;                   \
        unsigned _x = _rr.x ^ _rr.y;                                      \
        if (_x) {  /* warp-uniform, ~9% of windows */                     \
            if (_x & 0x0000FF00u) {                                       \
                float2* _q = (float2*)(accbase + __byte_perm(_rr.y, 0, 0x4414)); \
                float2 _a = *_q;                                          \
                _a.x = fminf(_a.x, (F4).y); _a.y = fmaxf(_a.y, (F4).y);   \
                *_q = _a;                                                 \
            }                                                             \
            if (_x & 0x00FF0000u) {                                       \
                float2* _q = (float2*)(accbase + __byte_perm(_rr.y, 0, 0x4424)); \
                float2 _a = *_q;                                          \
                _a.x = fminf(_a.x, (F4).z); _a.y = fmaxf(_a.y, (F4).z);   \
                *_q = _a;                                                 \
            }                                                             \
            if (_x & 0xFF000000u) {                                       \
                float2* _q = (float2*)(accbase + __byte_perm(_rr.y, 0, 0x4434)); \
                float2 _a = *_q;                                          \
                _a.x = fminf(_a.x, (F4).w); _a.y = fmaxf(_a.y, (F4).w);   \
                *_q = _a;                                                 \
            }                                                             \
        }                                                                 \
    } while (0)

    // 32-column superbatches: 8 LDG.128 issued back-to-back, prefetch dist 1.
    float4 A[8];
    #pragma unroll
    for (int i = 0; i < 8; i++) A[i] = rp[i];

    #pragma unroll 1
    for (int j = 0; j < NB; j++) {
        float4 P[8];
        if (j + 1 < NB) {
            const float4* np = rp + (j + 1) * 8;
            #pragma unroll
            for (int i = 0; i < 8; i++) P[i] = np[i];
        }
        const int wb = j * 8;
        WIN(A[0], wb + 0); WIN(A[1], wb + 1);
        WIN(A[2], wb + 2); WIN(A[3], wb + 3);
        WIN(A[4], wb + 4); WIN(A[5], wb + 5);
        WIN(A[6], wb + 6); WIN(A[7], wb + 7);
        #pragma unroll
        for (int i = 0; i < 8; i++) A[i] = P[i];
    }
    #undef WIN

    // ---- Flush: vectorized plain stores to unique partial slots ----
    {
        float4* pp = (float4*)&g_part[((size_t)bx * ROWS + row) * NG];
        #pragma unroll
        for (int g = 0; g < NG; g += 2) {
            float2 a = sacc[g * TPB + t];
            float2 b = sacc[(g + 1) * TPB + t];
            pp[g >> 1] = make_float4(a.x, a.y, b.x, b.y);
        }
    }

    // ---- Arrival protocol: last block of this row-set finalizes ----
    __threadfence();
    unsigned old = 0;
    if (t == 0) old = atomicAdd(&g_cnt[by], 1u);
    old = __shfl_sync(0xFFFFFFFFu, old, 0);
    if (old != NCHUNK - 1) return;

    __threadfence();            // acquire: all blocks' partials now visible
    if (t == 0) g_cnt[by] = 0;  // self-reset for next graph replay

    const float rcp15 = __uint_as_float(0x3D888889u);  // XLA's rounded 1/15
    const int rbase = by * TPB;

    // Lane t owns groups {2t, 2t+1}; loop rows. Coalesced 512B float4 loads.
    for (int r = 0; r < TPB; r++) {
        size_t base = ((size_t)rbase + r) * NG;
        const float4* q0 = (const float4*)&g_part[base];
        float4 a = q0[t];   // {min(2t), max(2t), min(2t+1), max(2t+1)} chunk 0
        #pragma unroll
        for (int c = 1; c < NCHUNK; c++) {
            const float4* qc = (const float4*)&g_part[(size_t)c * ROWS * NG + base];
            float4 b = qc[t];
            a.x = fminf(a.x, b.x); a.y = fmaxf(a.y, b.y);
            a.z = fminf(a.z, b.z); a.w = fmaxf(a.w, b.w);
        }
        float mn0 = fminf(a.x, 0.0f), mx0 = fmaxf(a.y, 0.0f);
        float mn1 = fminf(a.z, 0.0f), mx1 = fmaxf(a.w, 0.0f);
        float sc0 = fmaxf((mx0 - mn0) * rcp15, 1.1920929e-07f);
        float sc1 = fmaxf((mx1 - mn1) * rcp15, 1.1920929e-07f);
        float zp0 = rintf(-8.0f - __fdiv_rn(mn0, sc0));
        float zp1 = rintf(-8.0f - __fdiv_rn(mn1, sc1));
        zp0 = fminf(fmaxf(zp0, -8.0f), 7.0f);
        zp1 = fminf(fmaxf(zp1, -8.0f), 7.0f);
        int o = (rbase + r) * NG + 2 * t;
        ((float2*)(out + o))[0]        = make_float2(sc0, sc1);   // scale
        ((float2*)(out + NOUT + o))[0] = make_float2(zp0, zp1);   // zero_point
    }
}

extern "C" void kernel_launch(void* const* d_in, const int* in_sizes, int n_in,
                              void* d_out, int out_size) {
    const float* obs  = (const float*)d_in[0];
    const int*   gidx = (const int*)d_in[1];
    float* out = (float*)d_out;

    obs_prep_kernel<<<NWIN / 256, 256>>>(gidx);

    dim3 grid(NCHUNK, NROWBLK);   // 8 x 256 = 2048 blocks
    obs_fused_kernel<<<grid, TPB>>>(obs, gidx, out);
}

// round 9
// speedup vs baseline: 1.1082x; 1.1082x over previous
#include <cuda_runtime.h>
#include <cuda_bf16.h>
#include <math_constants.h>

#define ROWS 8192
#define COLS 8192
#define NG   64
#define TPB  32                       // one warp; thread t owns row t (via transpose)
#define CCHUNK 512                    // columns per block
#define TC    64                      // tile columns
#define NT    (CCHUNK / TC)           // 8 tiles per chunk
#define WPC   (CCHUNK / 4)            // 128 windows per chunk
#define NWIN  (COLS / 4)              // 2048 windows total
#define NCHUNK (COLS / CCHUNK)        // 16
#define NROWBLK (ROWS / TPB)          // 256
#define NOUT (ROWS * NG)              // 524288 per output tensor
#define BSTRIDE 65                    // smem tile row stride (words), odd -> conflict-free

// Partial min/max per (chunk, row, group): plain stores, no atomics. 67 MB.
__device__ float2   g_part[(size_t)NCHUNK * ROWS * NG];
__device__ unsigned g_cnt[NROWBLK];
// Per-window packed group ids: raw, and dup-remapped (dups -> group 64).
__device__ unsigned g_rawp[NWIN];
__device__ unsigned g_remp[NWIN];

// ---- Prep: detect duplicate groups within each aligned 4-column window ----
__global__ void obs_prep_kernel(const int* __restrict__ gidx) {
    int w = blockIdx.x * blockDim.x + threadIdx.x;
    if (w >= NWIN) return;
    int4 g = ((const int4*)gidx)[w];
    unsigned b0 = (unsigned)g.x, b1 = (unsigned)g.y;
    unsigned b2 = (unsigned)g.z, b3 = (unsigned)g.w;
    unsigned r1 = (b1 == b0) ? 64u : b1;
    unsigned r2 = (b2 == b0 || b2 == b1) ? 64u : b2;
    unsigned r3 = (b3 == b0 || b3 == b1 || b3 == b2) ? 64u : b3;
    g_rawp[w] = b0 | (b1 << 8) | (b2 << 16) | (b3 << 24);
    g_remp[w] = b0 | (r1 << 8) | (r2 << 16) | (r3 << 24);
}

__global__ __launch_bounds__(TPB, 6) void obs_fused_kernel(
    const float* __restrict__ obs, const int* __restrict__ gidx,
    float* __restrict__ out)
{
    __shared__ float2 sacc[65 * TPB];                 // 16.6 KB (group 64 = dup sink)
    __shared__ float  sbuf[2][TPB * BSTRIDE];         // 2 x 8.3 KB transposed tiles
    __shared__ __align__(8) uint2 swin[WPC];          // 1 KB {remapped, raw}

    const int t  = threadIdx.x;
    const int bx = blockIdx.x;          // chunk id
    const int by = blockIdx.y;          // row-block id
    const int c0 = bx * CCHUNK;
    const int rowbase = by * TPB;

    #pragma unroll
    for (int i = t; i < WPC; i += TPB)
        swin[i] = make_uint2(g_remp[bx * WPC + i], g_rawp[bx * WPC + i]);
    #pragma unroll
    for (int g = 0; g < 65; g++)
        sacc[g * TPB + t] = make_float2(CUDART_INF_F, -CUDART_INF_F);

    const float* base = obs + (size_t)rowbase * COLS + c0;
    char* accbase = (char*)sacc + t * 8;   // lane-private column of table

    // Coalesced tile staging: row-group rg = 8 rows; lane t loads col q*32+t.
    #define LOADRG(R, NB, RG) do {                                        \
        _Pragma("unroll")                                                 \
        for (int _i = 0; _i < 8; _i++) {                                  \
            const float* _r = (NB) + (size_t)((RG) * 8 + _i) * COLS;      \
            (R)[_i * 2 + 0] = _r[t];                                      \
            (R)[_i * 2 + 1] = _r[32 + t];                                 \
        }                                                                 \
    } while (0)
    #define STSRG(R, BUF, RG) do {                                        \
        _Pragma("unroll")                                                 \
        for (int _i = 0; _i < 8; _i++) {                                  \
            (BUF)[((RG) * 8 + _i) * BSTRIDE + t]      = (R)[_i * 2 + 0];  \
            (BUF)[((RG) * 8 + _i) * BSTRIDE + 32 + t] = (R)[_i * 2 + 1];  \
        }                                                                 \
    } while (0)

    // Dup-free batched table RMW for one 4-column window (R8 machinery).
    #define WIN(F4, WI) do {                                              \
        uint2 _rr = swin[(WI)];                                           \
        float2* _p0 = (float2*)(accbase + __byte_perm(_rr.x, 0, 0x4404)); \
        float2* _p1 = (float2*)(accbase + __byte_perm(_rr.x, 0, 0x4414)); \
        float2* _p2 = (float2*)(accbase + __byte_perm(_rr.x, 0, 0x4424)); \
        float2* _p3 = (float2*)(accbase + __byte_perm(_rr.x, 0, 0x4434)); \
        float2 _m0 = *_p0, _m1 = *_p1, _m2 = *_p2, _m3 = *_p3;            \
        _m0.x = fminf(_m0.x, (F4).x); _m0.y = fmaxf(_m0.y, (F4).x);       \
        _m1.x = fminf(_m1.x, (F4).y); _m1.y = fmaxf(_m1.y, (F4).y);       \
        _m2.x = fminf(_m2.x, (F4).z); _m2.y = fmaxf(_m2.y, (F4).z);       \
        _m3.x = fminf(_m3.x, (F4).w); _m3.y = fmaxf(_m3.y, (F4).w);       \
        *_p0 = _m0; *_p1 = _m1; *_p2 = _m2; *_p3 = _m3;                   \
        unsigned _x = _rr.x ^ _rr.y;                                      \
        if (_x) {  /* warp-uniform, rare */                               \
            if (_x & 0x0000FF00u) {                                       \
                float2* _q = (float2*)(accbase + __byte_perm(_rr.y, 0, 0x4414)); \
                float2 _a = *_q;                                          \
                _a.x = fminf(_a.x, (F4).y); _a.y = fmaxf(_a.y, (F4).y);   \
                *_q = _a;                                                 \
            }                                                             \
            if (_x & 0x00FF0000u) {                                       \
                float2* _q = (float2*)(accbase + __byte_perm(_rr.y, 0, 0x4424)); \
                float2 _a = *_q;                                          \
                _a.x = fminf(_a.x, (F4).z); _a.y = fmaxf(_a.y, (F4).z);   \
                *_q = _a;                                                 \
            }                                                             \
            if (_x & 0xFF000000u) {                                       \
                float2* _q = (float2*)(accbase + __byte_perm(_rr.y, 0, 0x4434)); \
                float2 _a = *_q;                                          \
                _a.x = fminf(_a.x, (F4).w); _a.y = fmaxf(_a.y, (F4).w);   \
                *_q = _a;                                                 \
            }                                                             \
        }                                                                 \
    } while (0)

    // Prologue: stage tile 0 into sbuf[0], depth-2 pipelined.
    {
        float A[16], B[16];
        LOADRG(A, base, 0); LOADRG(B, base, 1);
        STSRG(A, sbuf[0], 0);
        LOADRG(A, base, 2);
        STSRG(B, sbuf[0], 1);
        LOADRG(B, base, 3);
        STSRG(A, sbuf[0], 2);
        STSRG(B, sbuf[0], 3);
    }
    __syncwarp();

    // Main: process tile from cur while staging next tile into nxt.
    #pragma unroll 1
    for (int tile = 0; tile < NT; tile++) {
        const float* cur = sbuf[tile & 1];
        float*       nxt = sbuf[(tile + 1) & 1];
        const float* nb  = base + (tile + 1) * TC;
        const bool more = (tile + 1 < NT);
        const float* myrow = cur + t * BSTRIDE;   // thread t's row
        const int wbase = tile * (TC / 4);

        #pragma unroll
        for (int rg = 0; rg < 4; rg++) {
            float Rg[16];
            if (more) LOADRG(Rg, nb, rg);
            #pragma unroll
            for (int w = 0; w < 4; w++) {
                const int cb = (rg * 4 + w) * 4;
                float4 f;
                f.x = myrow[cb + 0];
                f.y = myrow[cb + 1];
                f.z = myrow[cb + 2];
                f.w = myrow[cb + 3];
                WIN(f, wbase + rg * 4 + w);
            }
            if (more) STSRG(Rg, nxt, rg);
        }
        __syncwarp();
    }
    #undef WIN
    #undef LOADRG
    #undef STSRG

    // ---- Flush: vectorized plain stores to unique partial slots ----
    {
        const int row = rowbase + t;
        float4* pp = (float4*)&g_part[((size_t)bx * ROWS + row) * NG];
        #pragma unroll
        for (int g = 0; g < NG; g += 2) {
            float2 a = sacc[g * TPB + t];
            float2 b = sacc[(g + 1) * TPB + t];
            pp[g >> 1] = make_float4(a.x, a.y, b.x, b.y);
        }
    }

    // ---- Arrival protocol: last block of this row-set finalizes ----
    __threadfence();
    unsigned old = 0;
    if (t == 0) old = atomicAdd(&g_cnt[by], 1u);
    old = __shfl_sync(0xFFFFFFFFu, old, 0);
    if (old != NCHUNK - 1) return;

    __threadfence();            // acquire: all blocks' partials now visible
    if (t == 0) g_cnt[by] = 0;  // self-reset for next graph replay

    const float rcp15 = __uint_as_float(0x3D888889u);  // XLA's rounded 1/15

    // Lane t owns groups {2t, 2t+1}; loop rows. Coalesced 512B float4 loads.
    for (int r = 0; r < TPB; r++) {
        size_t bse = ((size_t)rowbase + r) * NG;
        const float4* q0 = (const float4*)&g_part[bse];
        float4 a = q0[t];
        #pragma unroll
        for (int c = 1; c < NCHUNK; c++) {
            const float4* qc = (const float4*)&g_part[(size_t)c * ROWS * NG + bse];
            float4 b = qc[t];
            a.x = fminf(a.x, b.x); a.y = fmaxf(a.y, b.y);
            a.z = fminf(a.z, b.z); a.w = fmaxf(a.w, b.w);
        }
        float mn0 = fminf(a.x, 0.0f), mx0 = fmaxf(a.y, 0.0f);
        float mn1 = fminf(a.z, 0.0f), mx1 = fmaxf(a.w, 0.0f);
        float sc0 = fmaxf((mx0 - mn0) * rcp15, 1.1920929e-07f);
        float sc1 = fmaxf((mx1 - mn1) * rcp15, 1.1920929e-07f);
        float zp0 = rintf(-8.0f - __fdiv_rn(mn0, sc0));
        float zp1 = rintf(-8.0f - __fdiv_rn(mn1, sc1));
        zp0 = fminf(fmaxf(zp0, -8.0f), 7.0f);
        zp1 = fminf(fmaxf(zp1, -8.0f), 7.0f);
        int o = (rowbase + r) * NG + 2 * t;
        ((float2*)(out + o))[0]        = make_float2(sc0, sc1);   // scale
        ((float2*)(out + NOUT + o))[0] = make_float2(zp0, zp1);   // zero_point
    }
}

extern "C" void kernel_launch(void* const* d_in, const int* in_sizes, int n_in,
                              void* d_out, int out_size) {
    const float* obs  = (const float*)d_in[0];
    const int*   gidx = (const int*)d_in[1];
    float* out = (float*)d_out;

    obs_prep_kernel<<<NWIN / 256, 256>>>(gidx);

    dim3 grid(NCHUNK, NROWBLK);   // 16 x 256 = 4096 blocks
    obs_fused_kernel<<<grid, TPB>>>(obs, gidx, out);
}

// round 10
// speedup vs baseline: 1.2187x; 1.0997x over previous
#include <cuda_runtime.h>
#include <cuda_bf16.h>
#include <math_constants.h>

#define ROWS 8192
#define COLS 8192
#define NG   64
#define TPB  32                       // one warp; thread t owns row t (via transpose)
#define CCHUNK 512                    // columns per block
#define TC    32                      // tile columns
#define NT    (CCHUNK / TC)           // 16 tiles per chunk
#define WPC   (CCHUNK / 4)            // 128 windows per chunk
#define NWIN  (COLS / 4)              // 2048 windows total
#define NCHUNK (COLS / CCHUNK)        // 16
#define NROWBLK (ROWS / TPB)          // 256
#define NOUT (ROWS * NG)              // 524288 per output tensor
#define BSTRIDE 36                    // smem tile row stride in words (float4-aligned,
                                      // (r+c4)%8 bank groups -> 4-phase floor everywhere)

// Partial min/max per (chunk, row, group): plain stores, no atomics. 67 MB.
__device__ float2   g_part[(size_t)NCHUNK * ROWS * NG];
__device__ unsigned g_cnt[NROWBLK];
// Per-window packed group ids: raw, and dup-remapped (dups -> group 64).
__device__ unsigned g_rawp[NWIN];
__device__ unsigned g_remp[NWIN];

// ---- Prep: detect duplicate groups within each aligned 4-column window ----
__global__ void obs_prep_kernel(const int* __restrict__ gidx) {
    int w = blockIdx.x * blockDim.x + threadIdx.x;
    if (w >= NWIN) return;
    int4 g = ((const int4*)gidx)[w];
    unsigned b0 = (unsigned)g.x, b1 = (unsigned)g.y;
    unsigned b2 = (unsigned)g.z, b3 = (unsigned)g.w;
    unsigned r1 = (b1 == b0) ? 64u : b1;
    unsigned r2 = (b2 == b0 || b2 == b1) ? 64u : b2;
    unsigned r3 = (b3 == b0 || b3 == b1 || b3 == b2) ? 64u : b3;
    g_rawp[w] = b0 | (b1 << 8) | (b2 << 16) | (b3 << 24);
    g_remp[w] = b0 | (r1 << 8) | (r2 << 16) | (r3 << 24);
}

__global__ __launch_bounds__(TPB, 10) void obs_fused_kernel(
    const float* __restrict__ obs, const int* __restrict__ gidx,
    float* __restrict__ out)
{
    __shared__ float2 sacc[65 * TPB];                 // 16.6 KB (group 64 = dup sink)
    __shared__ __align__(16) float sbuf[TPB * BSTRIDE];  // 4.6 KB single tile buffer
    __shared__ __align__(8) uint2 swin[WPC];          // 1 KB {remapped, raw}

    const int t  = threadIdx.x;
    const int bx = blockIdx.x;          // chunk id
    const int by = blockIdx.y;          // row-block id
    const int c0 = bx * CCHUNK;
    const int rowbase = by * TPB;
    const int sr = t >> 3;              // staging: row within quad (0..3)
    const int sc = t & 7;               // staging: float4 column (0..7)

    #pragma unroll
    for (int i = t; i < WPC; i += TPB)
        swin[i] = make_uint2(g_remp[bx * WPC + i], g_rawp[bx * WPC + i]);
    #pragma unroll
    for (int g = 0; g < 65; g++)
        sacc[g * TPB + t] = make_float2(CUDART_INF_F, -CUDART_INF_F);

    // Staging base: lane covers (row = 4i+sr, float4 col sc) of the tile.
    const float* gbase = obs + (size_t)(rowbase + sr) * COLS + c0 + sc * 4;

    // Load tile TI into registers: 8x LDG.128, 4 rows per instr, coalesced.
    #define LDTILE(A, TI) do {                                            \
        _Pragma("unroll")                                                 \
        for (int _i = 0; _i < 8; _i++)                                    \
            (A)[_i] = *(const float4*)(gbase + (size_t)_i * 4 * COLS + (TI) * TC); \
    } while (0)
    // Store registers into smem tile: 8x STS.128, 4-phase floor.
    #define STTILE(A) do {                                                \
        _Pragma("unroll")                                                 \
        for (int _i = 0; _i < 8; _i++)                                    \
            *(float4*)&sbuf[(_i * 4 + sr) * BSTRIDE + sc * 4] = (A)[_i];  \
    } while (0)

    char* accbase = (char*)sacc + t * 8;   // lane-private column of table

    // Dup-free batched table RMW for one 4-column window.
    #define WIN(F4, WI) do {                                              \
        uint2 _rr = swin[(WI)];                                           \
        float2* _p0 = (float2*)(accbase + __byte_perm(_rr.x, 0, 0x4404)); \
        float2* _p1 = (float2*)(accbase + __byte_perm(_rr.x, 0, 0x4414)); \
        float2* _p2 = (float2*)(accbase + __byte_perm(_rr.x, 0, 0x4424)); \
        float2* _p3 = (float2*)(accbase + __byte_perm(_rr.x, 0, 0x4434)); \
        float2 _m0 = *_p0, _m1 = *_p1, _m2 = *_p2, _m3 = *_p3;            \
        _m0.x = fminf(_m0.x, (F4).x); _m0.y = fmaxf(_m0.y, (F4).x);       \
        _m1.x = fminf(_m1.x, (F4).y); _m1.y = fmaxf(_m1.y, (F4).y);       \
        _m2.x = fminf(_m2.x, (F4).z); _m2.y = fmaxf(_m2.y, (F4).z);       \
        _m3.x = fminf(_m3.x, (F4).w); _m3.y = fmaxf(_m3.y, (F4).w);       \
        *_p0 = _m0; *_p1 = _m1; *_p2 = _m2; *_p3 = _m3;                   \
        unsigned _x = _rr.x ^ _rr.y;                                      \
        if (_x) {  /* warp-uniform, ~9% of windows */                     \
            if (_x & 0x0000FF00u) {                                       \
                float2* _q = (float2*)(accbase + __byte_perm(_rr.y, 0, 0x4414)); \
                float2 _a = *_q;                                          \
                _a.x = fminf(_a.x, (F4).y); _a.y = fmaxf(_a.y, (F4).y);   \
                *_q = _a;                                                 \
            }                                                             \
            if (_x & 0x00FF0000u) {                                       \
                float2* _q = (float2*)(accbase + __byte_perm(_rr.y, 0, 0x4424)); \
                float2 _a = *_q;                                          \
                _a.x = fminf(_a.x, (F4).z); _a.y = fmaxf(_a.y, (F4).z);   \
                *_q = _a;                                                 \
            }                                                             \
            if (_x & 0xFF000000u) {                                       \
                float2* _q = (float2*)(accbase + __byte_perm(_rr.y, 0, 0x4434)); \
                float2 _a = *_q;                                          \
                _a.x = fminf(_a.x, (F4).w); _a.y = fmaxf(_a.y, (F4).w);   \
                *_q = _a;                                                 \
            }                                                             \
        }                                                                 \
    } while (0)

    float4 A[8];
    LDTILE(A, 0);

    #pragma unroll 1
    for (int tile = 0; tile < NT; tile++) {
        STTILE(A);                       // write tile (data already arrived)
        if (tile + 1 < NT)
            LDTILE(A, tile + 1);         // prefetch next: ~full tile of distance
        __syncwarp();

        const float* myrow = sbuf + t * BSTRIDE;   // thread t's row, 8 float4s
        const int wbase = tile * 8;
        #pragma unroll
        for (int w = 0; w < 8; w++) {
            float4 f = *(const float4*)&myrow[w * 4];   // LDS.128, 4-phase floor
            WIN(f, wbase + w);
        }
        __syncwarp();                    // tile fully consumed before overwrite
    }
    #undef WIN
    #undef LDTILE
    #undef STTILE

    // ---- Flush: vectorized plain stores to unique partial slots ----
    {
        const int row = rowbase + t;
        float4* pp = (float4*)&g_part[((size_t)bx * ROWS + row) * NG];
        #pragma unroll
        for (int g = 0; g < NG; g += 2) {
            float2 a = sacc[g * TPB + t];
            float2 b = sacc[(g + 1) * TPB + t];
            pp[g >> 1] = make_float4(a.x, a.y, b.x, b.y);
        }
    }

    // ---- Arrival protocol: last block of this row-set finalizes ----
    __threadfence();
    unsigned old = 0;
    if (t == 0) old = atomicAdd(&g_cnt[by], 1u);
    old = __shfl_sync(0xFFFFFFFFu, old, 0);
    if (old != NCHUNK - 1) return;

    __threadfence();            // acquire: all blocks' partials now visible
    if (t == 0) g_cnt[by] = 0;  // self-reset for next graph replay

    const float rcp15 = __uint_as_float(0x3D888889u);  // XLA's rounded 1/15

    // Lane t owns groups {2t, 2t+1}; loop rows. Coalesced 512B float4 loads.
    for (int r = 0; r < TPB; r++) {
        size_t bse = ((size_t)rowbase + r) * NG;
        const float4* q0 = (const float4*)&g_part[bse];
        float4 a = q0[t];
        #pragma unroll
        for (int c = 1; c < NCHUNK; c++) {
            const float4* qc = (const float4*)&g_part[(size_t)c * ROWS * NG + bse];
            float4 b = qc[t];
            a.x = fminf(a.x, b.x); a.y = fmaxf(a.y, b.y);
            a.z = fminf(a.z, b.z); a.w = fmaxf(a.w, b.w);
        }
        float mn0 = fminf(a.x, 0.0f), mx0 = fmaxf(a.y, 0.0f);
        float mn1 = fminf(a.z, 0.0f), mx1 = fmaxf(a.w, 0.0f);
        float sc0 = fmaxf((mx0 - mn0) * rcp15, 1.1920929e-07f);
        float sc1 = fmaxf((mx1 - mn1) * rcp15, 1.1920929e-07f);
        float zp0 = rintf(-8.0f - __fdiv_rn(mn0, sc0));
        float zp1 = rintf(-8.0f - __fdiv_rn(mn1, sc1));
        zp0 = fminf(fmaxf(zp0, -8.0f), 7.0f);
        zp1 = fminf(fmaxf(zp1, -8.0f), 7.0f);
        int o = (rowbase + r) * NG + 2 * t;
        ((float2*)(out + o))[0]        = make_float2(sc0, sc1);   // scale
        ((float2*)(out + NOUT + o))[0] = make_float2(zp0, zp1);   // zero_point
    }
}

extern "C" void kernel_launch(void* const* d_in, const int* in_sizes, int n_in,
                              void* d_out, int out_size) {
    const float* obs  = (const float*)d_in[0];
    const int*   gidx = (const int*)d_in[1];
    float* out = (float*)d_out;

    obs_prep_kernel<<<NWIN / 256, 256>>>(gidx);

    dim3 grid(NCHUNK, NROWBLK);   // 16 x 256 = 4096 blocks
    obs_fused_kernel<<<grid, TPB>>>(obs, gidx, out);
}